// round 1
// baseline (speedup 1.0000x reference)
#include <cuda_runtime.h>
#include <math.h>

#define B_  16
#define S_  8
#define H_  2048
#define NH_ 16
#define HD_ 128
#define ML_ 4104          // MAX_LEN
#define FULLMASK 0xffffffffu

// Scratch (no allocations allowed; __device__ globals per rules)
__device__ float g_q[B_ * NH_ * S_ * HD_];     // 262144 floats: q in [b][h][s][d]
__device__ float g_attn[B_ * S_ * H_];         // 262144 floats: attn out in [b*s][h*128+d]

// ---------------------------------------------------------------------------
// GEMM1: qkv[128,6144] = x[128,2048] @ in_w[6144,2048]^T + in_b
// BM=BN=64, BK=16, 256 threads, 4x4 microtile. Epilogue scatters q -> g_q,
// k/v -> d_out cache regions at cache_pos.
// ---------------------------------------------------------------------------
__global__ __launch_bounds__(256)
void qkv_gemm_kernel(const float* __restrict__ x, const float* __restrict__ w,
                     const float* __restrict__ bias, const int* __restrict__ cpp,
                     float* __restrict__ out_k, float* __restrict__ out_v)
{
    __shared__ float As[16][64];
    __shared__ float Bs[16][64];
    const int t  = threadIdx.x;
    const int m0 = blockIdx.y * 64, n0 = blockIdx.x * 64;
    const int tx = t & 15, ty = t >> 4;
    const int lr = t >> 2, lc = (t & 3) << 2;
    float acc[4][4] = {};
    const float* xp = x + (size_t)(m0 + lr) * 2048 + lc;
    const float* wp = w + (size_t)(n0 + lr) * 2048 + lc;
    for (int k0 = 0; k0 < 2048; k0 += 16) {
        float4 a = *(const float4*)(xp + k0);
        float4 b = *(const float4*)(wp + k0);
        As[lc+0][lr] = a.x; As[lc+1][lr] = a.y; As[lc+2][lr] = a.z; As[lc+3][lr] = a.w;
        Bs[lc+0][lr] = b.x; Bs[lc+1][lr] = b.y; Bs[lc+2][lr] = b.z; Bs[lc+3][lr] = b.w;
        __syncthreads();
        #pragma unroll
        for (int kk = 0; kk < 16; kk++) {
            float4 a4 = *(const float4*)&As[kk][ty << 2];
            float4 b4 = *(const float4*)&Bs[kk][tx << 2];
            float av[4] = {a4.x, a4.y, a4.z, a4.w};
            float bv[4] = {b4.x, b4.y, b4.z, b4.w};
            #pragma unroll
            for (int i = 0; i < 4; i++)
                #pragma unroll
                for (int j = 0; j < 4; j++)
                    acc[i][j] = fmaf(av[i], bv[j], acc[i][j]);
        }
        __syncthreads();
    }
    const int cp = *cpp;
    #pragma unroll
    for (int i = 0; i < 4; i++) {
        int m = m0 + (ty << 2) + i;
        int bb = m >> 3, s = m & 7;
        #pragma unroll
        for (int j = 0; j < 4; j++) {
            int n = n0 + (tx << 2) + j;
            float v = acc[i][j] + bias[n];
            if (n < 2048) {
                int h = n >> 7, d = n & 127;
                g_q[(size_t)(((bb << 4) + h) * 8 + s) * 128 + d] = v;
            } else if (n < 4096) {
                int c = n - 2048; int h = c >> 7, d = c & 127;
                out_k[((size_t)((bb << 4) + h) * ML_ + cp + s) * 128 + d] = v;
            } else {
                int c = n - 4096; int h = c >> 7, d = c & 127;
                out_v[((size_t)((bb << 4) + h) * ML_ + cp + s) * 128 + d] = v;
            }
        }
    }
}

// ---------------------------------------------------------------------------
// Fused cache-copy + flash attention.
// 1 block per (b,h) = 256 blocks, 256 threads.
// - q[8][128] held in registers: q4[8] float4 per lane.
// - K is read from global ONCE per row: while copying to d_out, the same warp
//   computes all 8 query dots via shuffle reduction (no smem for K).
// - V staged in smem; PV with 2 queries per thread, j-range split in halves.
// ---------------------------------------------------------------------------
__global__ __launch_bounds__(256)
void attn_kernel(const float* __restrict__ k_in, const float* __restrict__ v_in,
                 const int* __restrict__ cpp,
                 float* __restrict__ k_out, float* __restrict__ v_out)
{
    const int t    = threadIdx.x;
    const int lane = t & 31;
    const int w    = t >> 5;
    const int bh   = blockIdx.x;
    const int cp   = *cpp;
    const int valid = cp + S_;

    const float4* kin4  = (const float4*)k_in + (size_t)bh * ML_ * 32;
    const float4* vin4  = (const float4*)v_in + (size_t)bh * ML_ * 32;
    float4*       kout4 = (float4*)k_out + (size_t)bh * ML_ * 32;
    float4*       vout4 = (float4*)v_out + (size_t)bh * ML_ * 32;

    // load 8 query rows into registers (lane owns its float4 slice of each row)
    float4 q4[8];
    {
        const float4* qp = (const float4*)g_q + (size_t)bh * 8 * 32;
        #pragma unroll
        for (int q = 0; q < 8; q++) q4[q] = qp[q * 32 + lane];
    }

    __shared__ float  ss[8][64];       // scores -> probabilities
    __shared__ float4 vs[64 * 32];     // V chunk (32KB), reused as combine buffer
    __shared__ float  m_s[8], l_s[8], fac_s[8];
    if (t < 8) { m_s[t] = -INFINITY; l_s[t] = 0.f; fac_s[t] = 1.f; }
    __syncthreads();

    const int half = t >> 7;           // 0/1 : which half of j-range
    const int qg   = (t >> 5) & 3;     // owns queries qg and qg+4
    const int dg   = t & 31;           // float4 group in head dim
    float4 acc0 = make_float4(0.f, 0.f, 0.f, 0.f);
    float4 acc1 = make_float4(0.f, 0.f, 0.f, 0.f);

    const float scale = 0.08838834764831845f;   // 1/sqrt(128)

    for (int row0 = 0; row0 < 4160; row0 += 64) {     // 65 chunks covering 4104
        // ---- scores: warp w handles rows [w*8, w*8+8) of this chunk ----
        #pragma unroll
        for (int rr = 0; rr < 8; rr++) {
            int r = (w << 3) + rr;
            int p = row0 + r;
            float s[8];
            #pragma unroll
            for (int q = 0; q < 8; q++) s[q] = 0.f;
            if (p < ML_) {
                float4 kk;
                if (p < cp)         { kk = kin4[p * 32 + lane]; kout4[p * 32 + lane] = kk; }
                else if (p < valid) { kk = kout4[p * 32 + lane]; }
                else                { kk = kin4[p * 32 + lane]; kout4[p * 32 + lane] = kk; }
                #pragma unroll
                for (int q = 0; q < 8; q++)
                    s[q] = fmaf(q4[q].x, kk.x, fmaf(q4[q].y, kk.y,
                           fmaf(q4[q].z, kk.z, q4[q].w * kk.w)));
            }
            #pragma unroll
            for (int q = 0; q < 8; q++) {
                #pragma unroll
                for (int off = 16; off; off >>= 1)
                    s[q] += __shfl_xor_sync(FULLMASK, s[q], off);
            }
            if (lane == 0) {
                bool att = (p < valid);
                #pragma unroll
                for (int q = 0; q < 8; q++)
                    ss[q][r] = att ? s[q] * scale : -INFINITY;
            }
        }
        __syncthreads();

        // ---- online softmax: warp w owns query w ----
        {
            int q = w;
            float v0 = ss[q][lane], v1 = ss[q][lane + 32];
            float mx = fmaxf(v0, v1);
            #pragma unroll
            for (int off = 16; off; off >>= 1)
                mx = fmaxf(mx, __shfl_xor_sync(FULLMASK, mx, off));
            float m_old = m_s[q];
            float m_new = fmaxf(m_old, mx);
            float e0, e1, f;
            if (m_new == -INFINITY) { e0 = 0.f; e1 = 0.f; f = 1.f; }
            else {
                e0 = __expf(v0 - m_new);       // expf(-inf)=0 handles masked
                e1 = __expf(v1 - m_new);
                f  = __expf(m_old - m_new);    // m_old=-inf -> 0
            }
            ss[q][lane] = e0; ss[q][lane + 32] = e1;
            float sum = e0 + e1;
            #pragma unroll
            for (int off = 16; off; off >>= 1)
                sum += __shfl_xor_sync(FULLMASK, sum, off);
            if (lane == 0) {
                m_s[q]   = m_new;
                l_s[q]   = l_s[q] * f + sum;
                fac_s[q] = f;
            }
        }
        __syncthreads();

        // ---- V load (+ copy) into smem ----
        #pragma unroll
        for (int i = 0; i < 8; i++) {
            int idx = (i << 8) + t;
            int r = idx >> 5, c = idx & 31;
            int p = row0 + r;
            float4 val = make_float4(0.f, 0.f, 0.f, 0.f);
            if (p < cp)         { val = vin4[p * 32 + c]; vout4[p * 32 + c] = val; }
            else if (p < valid) { val = vout4[p * 32 + c]; }
            else if (p < ML_)   { val = vin4[p * 32 + c]; vout4[p * 32 + c] = val; }
            vs[idx] = val;
        }
        __syncthreads();

        // ---- PV accumulate (rescale by fac first) ----
        {
            float f0 = fac_s[qg], f1 = fac_s[qg + 4];
            acc0.x *= f0; acc0.y *= f0; acc0.z *= f0; acc0.w *= f0;
            acc1.x *= f1; acc1.y *= f1; acc1.z *= f1; acc1.w *= f1;
            const float*  p0r = &ss[qg][half << 5];
            const float*  p1r = &ss[qg + 4][half << 5];
            const float4* vr  = &vs[(half << 5) * 32 + dg];
            #pragma unroll
            for (int jj = 0; jj < 32; jj++) {
                float4 v4 = vr[jj * 32];
                float p0 = p0r[jj], p1 = p1r[jj];
                acc0.x = fmaf(p0, v4.x, acc0.x);
                acc0.y = fmaf(p0, v4.y, acc0.y);
                acc0.z = fmaf(p0, v4.z, acc0.z);
                acc0.w = fmaf(p0, v4.w, acc0.w);
                acc1.x = fmaf(p1, v4.x, acc1.x);
                acc1.y = fmaf(p1, v4.y, acc1.y);
                acc1.z = fmaf(p1, v4.z, acc1.z);
                acc1.w = fmaf(p1, v4.w, acc1.w);
            }
        }
        __syncthreads();
    }

    // combine the two j-halves, normalize, write to g_attn as [b*s][h*128+d]
    float4* po = vs;
    if (half == 1) {
        po[qg * 32 + dg]       = acc0;
        po[(qg + 4) * 32 + dg] = acc1;
    }
    __syncthreads();
    if (half == 0) {
        float4 o = po[qg * 32 + dg];
        acc0.x += o.x; acc0.y += o.y; acc0.z += o.z; acc0.w += o.w;
        o = po[(qg + 4) * 32 + dg];
        acc1.x += o.x; acc1.y += o.y; acc1.z += o.z; acc1.w += o.w;
        float il0 = 1.f / l_s[qg];
        float il1 = 1.f / l_s[qg + 4];
        int bb = bh >> 4, h = bh & 15;
        float4* ao = (float4*)g_attn;
        ao[(size_t)(bb * 8 + qg) * 512 + h * 32 + dg] =
            make_float4(acc0.x * il0, acc0.y * il0, acc0.z * il0, acc0.w * il0);
        ao[(size_t)(bb * 8 + qg + 4) * 512 + h * 32 + dg] =
            make_float4(acc1.x * il1, acc1.y * il1, acc1.z * il1, acc1.w * il1);
    }
}

// ---------------------------------------------------------------------------
// GEMM2: out[128,2048] = g_attn[128,2048] @ out_w[2048,2048]^T + out_b
// ---------------------------------------------------------------------------
__global__ __launch_bounds__(256)
void proj_gemm_kernel(const float* __restrict__ w, const float* __restrict__ bias,
                      float* __restrict__ out)
{
    __shared__ float As[16][64];
    __shared__ float Bs[16][64];
    const int t  = threadIdx.x;
    const int m0 = blockIdx.y * 64, n0 = blockIdx.x * 64;
    const int tx = t & 15, ty = t >> 4;
    const int lr = t >> 2, lc = (t & 3) << 2;
    float acc[4][4] = {};
    const float* xp = g_attn + (size_t)(m0 + lr) * 2048 + lc;
    const float* wp = w + (size_t)(n0 + lr) * 2048 + lc;
    for (int k0 = 0; k0 < 2048; k0 += 16) {
        float4 a = *(const float4*)(xp + k0);
        float4 b = *(const float4*)(wp + k0);
        As[lc+0][lr] = a.x; As[lc+1][lr] = a.y; As[lc+2][lr] = a.z; As[lc+3][lr] = a.w;
        Bs[lc+0][lr] = b.x; Bs[lc+1][lr] = b.y; Bs[lc+2][lr] = b.z; Bs[lc+3][lr] = b.w;
        __syncthreads();
        #pragma unroll
        for (int kk = 0; kk < 16; kk++) {
            float4 a4 = *(const float4*)&As[kk][ty << 2];
            float4 b4 = *(const float4*)&Bs[kk][tx << 2];
            float av[4] = {a4.x, a4.y, a4.z, a4.w};
            float bv[4] = {b4.x, b4.y, b4.z, b4.w};
            #pragma unroll
            for (int i = 0; i < 4; i++)
                #pragma unroll
                for (int j = 0; j < 4; j++)
                    acc[i][j] = fmaf(av[i], bv[j], acc[i][j]);
        }
        __syncthreads();
    }
    #pragma unroll
    for (int i = 0; i < 4; i++) {
        int m = m0 + (ty << 2) + i;
        #pragma unroll
        for (int j = 0; j < 4; j++) {
            int n = n0 + (tx << 2) + j;
            out[(size_t)m * 2048 + n] = acc[i][j] + bias[n];
        }
    }
}

// ---------------------------------------------------------------------------
extern "C" void kernel_launch(void* const* d_in, const int* in_sizes, int n_in,
                              void* d_out, int out_size)
{
    const float* x     = (const float*)d_in[0];
    const float* kc    = (const float*)d_in[1];
    const float* vc    = (const float*)d_in[2];
    const float* in_w  = (const float*)d_in[3];
    const float* in_b  = (const float*)d_in[4];
    const float* out_w = (const float*)d_in[5];
    const float* out_b = (const float*)d_in[6];
    const int*   cpp   = (const int*)d_in[7];

    float* out   = (float*)d_out;                         // [16,8,2048]
    float* out_k = out + (size_t)B_ * S_ * H_;            // [16,16,4104,128]
    float* out_v = out_k + (size_t)B_ * NH_ * ML_ * HD_;  // [16,16,4104,128]

    // 1) QKV projection; writes q->g_q, new k/v rows directly into out caches
    qkv_gemm_kernel<<<dim3(96, 2), 256>>>(x, in_w, in_b, cpp, out_k, out_v);
    // 2) fused cache copy + attention (reads old caches once, writes out caches)
    attn_kernel<<<256, 256>>>(kc, vc, cpp, out_k, out_v);
    // 3) output projection
    proj_gemm_kernel<<<dim3(32, 2), 256>>>(out_w, out_b, out);
}